// round 1
// baseline (speedup 1.0000x reference)
#include <cuda_runtime.h>

typedef unsigned long long ull;

// Packed fp32x2 helpers — ptxas will NOT auto-fuse 2x fmaf; must use PTX f32x2.
__device__ __forceinline__ ull pack2(float v) {
    ull r; asm("mov.b64 %0, {%1, %1};" : "=l"(r) : "f"(v)); return r;
}
__device__ __forceinline__ void ffma2(ull &d, ull a, ull b) {
    asm("fma.rn.f32x2 %0, %1, %2, %0;" : "+l"(d) : "l"(a), "l"(b));
}
__device__ __forceinline__ float2 unpk(ull v) {
    float2 f; asm("mov.b64 {%0, %1}, %2;" : "=f"(f.x), "=f"(f.y) : "l"(v)); return f;
}

#define SX 65        // x smem row stride (floats): 8*65 % 32 == 8 -> conflict-free
#define NB 128       // n rows per block
#define THREADS 128

// Shapes (fixed by problem):
//   x:      (N=65536, 25, 64) f32, row stride 1600 floats
//   weight: (4, 64, 64) f32
//   out:    (N, 35, 64) f32, row stride 2240 floats
// out[n, m, d] = sum_c x[n, m+1, c] * W[deg(m), c, d]  for m in 0..23
// out[n, 24..34, :] = 0

__global__ __launch_bounds__(THREADS)
void dwl_kernel(const float* __restrict__ x,
                const float* __restrict__ weight,
                float* __restrict__ out)
{
    const int m  = blockIdx.x;          // 0..24 (24 == zero-pad block)
    const int n0 = blockIdx.y * NB;
    const int t  = threadIdx.x;

    if (m == 24) {
        // zero-fill orders 24..34: 11*64 = 704 floats = 176 float4 per n row
        const float4 z = make_float4(0.f, 0.f, 0.f, 0.f);
        #pragma unroll 4
        for (int i = t; i < NB * 176; i += THREADS) {
            int r = i / 176;
            int j = i - r * 176;
            float4* p = (float4*)(out + (long long)(n0 + r) * 2240 + 1536);
            p[j] = z;
        }
        return;
    }

    extern __shared__ float smem[];
    float* xs = smem;                 // NB * SX floats
    float* ws = smem + NB * SX;       // 64 * 64 floats (stride 64)

    const int deg = (m >= 3) + (m >= 8) + (m >= 15);

    // Load this degree's 64x64 weight (contiguous) into smem
    const float4* W4 = (const float4*)(weight + deg * 4096);
    #pragma unroll
    for (int i = t; i < 1024; i += THREADS)
        ((float4*)ws)[i] = W4[i];

    // Load x tile: 128 rows (order m+1), 64 floats each, coalesced float4,
    // scalar-store into stride-65 smem (16 lanes per row -> consecutive banks, no conflict)
    const float* Xb = x + ((long long)n0 * 25 + (m + 1)) * 64;
    #pragma unroll
    for (int i = t; i < NB * 16; i += THREADS) {
        int r  = i >> 4;
        int k4 = (i & 15) << 2;
        float4 v = *(const float4*)(Xb + (long long)r * 1600 + k4);
        float* d = xs + r * SX + k4;
        d[0] = v.x; d[1] = v.y; d[2] = v.z; d[3] = v.w;
    }
    __syncthreads();

    // Thread tile: 8 rows x 8 cols (= 4 packed col-pairs)
    const int c8 = (t & 7) * 8;       // col base
    const int r0 = (t >> 3) * 8;      // row base

    ull acc[8][4];
    #pragma unroll
    for (int r = 0; r < 8; r++) {
        acc[r][0] = 0ull; acc[r][1] = 0ull; acc[r][2] = 0ull; acc[r][3] = 0ull;
    }

    #pragma unroll 4
    for (int k = 0; k < 64; k++) {
        // W row k, cols [c8, c8+8): two 16B loads = 4 pre-packed f32 pairs
        ulonglong2 wa = *(const ulonglong2*)(ws + k * 64 + c8);
        ulonglong2 wb = *(const ulonglong2*)(ws + k * 64 + c8 + 4);
        #pragma unroll
        for (int r = 0; r < 8; r++) {
            ull xb = pack2(xs[(r0 + r) * SX + k]);
            ffma2(acc[r][0], xb, wa.x);
            ffma2(acc[r][1], xb, wa.y);
            ffma2(acc[r][2], xb, wb.x);
            ffma2(acc[r][3], xb, wb.y);
        }
    }

    // Epilogue: 2 float4 stores per row
    #pragma unroll
    for (int r = 0; r < 8; r++) {
        float2 a0 = unpk(acc[r][0]);
        float2 a1 = unpk(acc[r][1]);
        float2 a2 = unpk(acc[r][2]);
        float2 a3 = unpk(acc[r][3]);
        float* o = out + (long long)(n0 + r0 + r) * 2240 + m * 64 + c8;
        *(float4*)(o)     = make_float4(a0.x, a0.y, a1.x, a1.y);
        *(float4*)(o + 4) = make_float4(a2.x, a2.y, a3.x, a3.y);
    }
}

extern "C" void kernel_launch(void* const* d_in, const int* in_sizes, int n_in,
                              void* d_out, int out_size)
{
    const float* x = (const float*)d_in[0];
    const float* w = (const float*)d_in[1];
    // Defensive: identify tensors by size (x is the big one)
    if (n_in >= 2 && in_sizes[0] < in_sizes[1]) {
        x = (const float*)d_in[1];
        w = (const float*)d_in[0];
    }
    float* out = (float*)d_out;

    const int nrows   = 65536;               // N
    const int smem_sz = (NB * SX + 64 * 64) * sizeof(float);  // 49664 B

    cudaFuncSetAttribute(dwl_kernel, cudaFuncAttributeMaxDynamicSharedMemorySize, smem_sz);

    dim3 grid(25, nrows / NB);   // 25 x 512
    dwl_kernel<<<grid, THREADS, smem_sz>>>(x, w, out);
}

// round 3
// speedup vs baseline: 1.1015x; 1.1015x over previous
#include <cuda_runtime.h>

typedef unsigned long long ull;

// Packed fp32x2 helpers — ptxas will NOT auto-fuse 2x fmaf; must use PTX f32x2.
__device__ __forceinline__ ull pack2(float v) {
    ull r; asm("mov.b64 %0, {%1, %1};" : "=l"(r) : "f"(v)); return r;
}
__device__ __forceinline__ void ffma2(ull &d, ull a, ull b) {
    asm("fma.rn.f32x2 %0, %1, %2, %0;" : "+l"(d) : "l"(a), "l"(b));
}
__device__ __forceinline__ float2 unpk(ull v) {
    float2 f; asm("mov.b64 {%0, %1}, %2;" : "=f"(f.x), "=f"(f.y) : "l"(v)); return f;
}

#define SX 68        // x smem row stride (floats): 272 B, 16B-aligned for LDS.128
#define NB 128       // n rows per block
#define THREADS 128

// Shapes (fixed by problem):
//   x:      (N=65536, 25, 64) f32, row stride 1600 floats
//   weight: (4, 64, 64) f32
//   out:    (N, 35, 64) f32, row stride 2240 floats
// out[n, m, d] = sum_c x[n, m+1, c] * W[deg(m), c, d]  for m in 0..23
// out[n, 24..34, :] = 0

__global__ __launch_bounds__(THREADS, 4)
void dwl_kernel(const float* __restrict__ x,
                const float* __restrict__ weight,
                float* __restrict__ out)
{
    const int m  = blockIdx.x;          // 0..24 (24 == zero-pad block)
    const int n0 = blockIdx.y * NB;
    const int t  = threadIdx.x;

    if (m == 24) {
        // zero-fill orders 24..34: 11*64 = 704 floats = 176 float4 per n row
        const float4 z = make_float4(0.f, 0.f, 0.f, 0.f);
        #pragma unroll 4
        for (int i = t; i < NB * 176; i += THREADS) {
            int r = i / 176;
            int j = i - r * 176;
            float4* p = (float4*)(out + (long long)(n0 + r) * 2240 + 1536);
            p[j] = z;
        }
        return;
    }

    extern __shared__ float smem[];
    float* xs = smem;                 // NB * SX floats
    float* ws = smem + NB * SX;       // 64 * 64 floats, quad-permuted per row

    const int deg = (m >= 3) + (m >= 8) + (m >= 15);

    // Load this degree's 64x64 weight into smem with quad permutation:
    // quad q (cols 4q..4q+3) of row k stored at position p = (q&1)*8 + (q>>1).
    // Lane-group g then reads its 8 cols as two LDS.128 at float offsets
    // g*4 and 32+g*4; per 8-lane phase the 8 groups span all 32 banks.
    const float4* W4 = (const float4*)(weight + deg * 4096);
    #pragma unroll
    for (int i = t; i < 1024; i += THREADS) {
        float4 v = W4[i];
        int k = i >> 4;
        int q = i & 15;
        int p = ((q & 1) << 3) | (q >> 1);
        *(float4*)(ws + k * 64 + p * 4) = v;
    }

    // Load x tile: 128 rows (order m+1), 64 floats each, coalesced float4
    // from gmem, float4 store into stride-68 smem (aligned, conflict-free phases)
    const float* Xb = x + ((long long)n0 * 25 + (m + 1)) * 64;
    #pragma unroll
    for (int i = t; i < NB * 16; i += THREADS) {
        int r  = i >> 4;
        int k4 = (i & 15) << 2;
        float4 v = *(const float4*)(Xb + (long long)r * 1600 + k4);
        *(float4*)(xs + r * SX + k4) = v;
    }
    __syncthreads();

    // Thread tile: 8 rows x 8 cols (= 4 packed col-pairs)
    const int g  = t & 7;             // col group (cols 8g..8g+7)
    const int r0 = (t >> 3) * 8;      // row base

    ull acc[8][4];
    #pragma unroll
    for (int r = 0; r < 8; r++) {
        acc[r][0] = 0ull; acc[r][1] = 0ull; acc[r][2] = 0ull; acc[r][3] = 0ull;
    }

    const float* wbase = ws + g * 4;

    #pragma unroll 2
    for (int k0 = 0; k0 < 64; k0 += 4) {
        // x: one LDS.128 per row covering 4 k values; 8-lane broadcast per
        // phase -> conflict-free
        float4 xv[8];
        #pragma unroll
        for (int r = 0; r < 8; r++)
            xv[r] = *(const float4*)(xs + (r0 + r) * SX + k0);

        #pragma unroll
        for (int kk = 0; kk < 4; kk++) {
            const float* wk = wbase + (k0 + kk) * 64;
            ulonglong2 wa = *(const ulonglong2*)(wk);        // cols 8g..8g+3
            ulonglong2 wb = *(const ulonglong2*)(wk + 32);   // cols 8g+4..8g+7
            #pragma unroll
            for (int r = 0; r < 8; r++) {
                float xval = (kk == 0) ? xv[r].x : (kk == 1) ? xv[r].y
                           : (kk == 2) ? xv[r].z : xv[r].w;
                ull xb = pack2(xval);
                ffma2(acc[r][0], xb, wa.x);
                ffma2(acc[r][1], xb, wa.y);
                ffma2(acc[r][2], xb, wb.x);
                ffma2(acc[r][3], xb, wb.y);
            }
        }
    }

    // Epilogue: 2 float4 stores per row
    #pragma unroll
    for (int r = 0; r < 8; r++) {
        float2 a0 = unpk(acc[r][0]);
        float2 a1 = unpk(acc[r][1]);
        float2 a2 = unpk(acc[r][2]);
        float2 a3 = unpk(acc[r][3]);
        float* o = out + (long long)(n0 + r0 + r) * 2240 + m * 64 + g * 8;
        *(float4*)(o)     = make_float4(a0.x, a0.y, a1.x, a1.y);
        *(float4*)(o + 4) = make_float4(a2.x, a2.y, a3.x, a3.y);
    }
}

extern "C" void kernel_launch(void* const* d_in, const int* in_sizes, int n_in,
                              void* d_out, int out_size)
{
    const float* x = (const float*)d_in[0];
    const float* w = (const float*)d_in[1];
    // Defensive: identify tensors by size (x is the big one)
    if (n_in >= 2 && in_sizes[0] < in_sizes[1]) {
        x = (const float*)d_in[1];
        w = (const float*)d_in[0];
    }
    float* out = (float*)d_out;

    const int nrows   = 65536;               // N
    const int smem_sz = (NB * SX + 64 * 64) * sizeof(float);  // 51200 B

    cudaFuncSetAttribute(dwl_kernel, cudaFuncAttributeMaxDynamicSharedMemorySize, smem_sz);

    dim3 grid(25, nrows / NB);   // 25 x 512
    dwl_kernel<<<grid, THREADS, smem_sz>>>(x, w, out);
}